// round 1
// baseline (speedup 1.0000x reference)
#include <cuda_runtime.h>
#include <cstdint>

// Problem constants
#define DNODES 128
#define HID    512
#define NSAMP  2048

// Tiling
#define TN       64      // samples per block
#define NCHUNK   128     // N (output) chunk per pass
#define KT       32      // K rows per staged B tile
#define THREADS  256     // 8 warps: 4 (M) x 2 (N)

// SMEM strides (floats), padded for conflict-free access
#define LDX   132        // xs:  64 x 132
#define LDH   516        // h1:  64 x 516
#define LDB   136        // Bs:  KT x 136 (x2 buffers)

#define XS_OFF   0
#define H1_OFF   (XS_OFF + TN * LDX)                 // 8448
#define BS_OFF   (H1_OFF + TN * LDH)                 // 41472
#define BS_TILE  (KT * LDB)                          // 4352
#define W2_OFF   (BS_OFF + 2 * BS_TILE)              // 50176
#define OUT_OFF  (W2_OFF + HID)                      // 50688
#define SMEM_FLOATS (OUT_OFF + TN)                   // 50752
#define SMEM_BYTES (SMEM_FLOATS * 4)                 // 203008

__device__ __forceinline__ float to_tf32(float x) {
    float r;
    asm("cvt.rna.tf32.f32 %0, %1;" : "=f"(r) : "f"(x));
    return r;
}

__device__ __forceinline__ float leaky(float x) {
    return x > 0.0f ? x : 0.01f * x;
}

__device__ __forceinline__ void mma_tf32(float c[4],
                                         uint32_t a0, uint32_t a1, uint32_t a2, uint32_t a3,
                                         uint32_t b0, uint32_t b1) {
    asm volatile(
        "mma.sync.aligned.m16n8k8.row.col.f32.tf32.tf32.f32 "
        "{%0,%1,%2,%3},{%4,%5,%6,%7},{%8,%9},{%0,%1,%2,%3};"
        : "+f"(c[0]), "+f"(c[1]), "+f"(c[2]), "+f"(c[3])
        : "r"(a0), "r"(a1), "r"(a2), "r"(a3), "r"(b0), "r"(b1));
}

// Stage one KT x 128 fp32 tile: global -> registers
__device__ __forceinline__ void stage_ldg(const float* __restrict__ src, int ld,
                                          float4 regs[4], int tid) {
#pragma unroll
    for (int q = 0; q < 4; q++) {
        int fid = tid + q * THREADS;          // 0..1023 float4 ids
        int r = fid >> 5;                     // 32 float4 per row
        int c4 = fid & 31;
        regs[q] = *reinterpret_cast<const float4*>(src + (size_t)r * ld + c4 * 4);
    }
}

// registers -> smem tile (tf32-rounded)
__device__ __forceinline__ void stage_sts(float* __restrict__ bs, float4 regs[4], int tid) {
#pragma unroll
    for (int q = 0; q < 4; q++) {
        int fid = tid + q * THREADS;
        int r = fid >> 5;
        int c4 = fid & 31;
        float4 v = regs[q];
        v.x = to_tf32(v.x); v.y = to_tf32(v.y); v.z = to_tf32(v.z); v.w = to_tf32(v.w);
        *reinterpret_cast<float4*>(bs + r * LDB + c4 * 4) = v;
    }
}

// One staged B tile worth of MMAs: warp computes 16(M) x 64(N), K = KT
__device__ __forceinline__ void gemm_tile(const float* __restrict__ As, int lda,
                                          const float* __restrict__ Bs,
                                          float acc[8][4],
                                          int k0, int arow, int bcol, int g, int t4) {
#pragma unroll
    for (int kk = 0; kk < KT; kk += 8) {
        int ka = k0 + kk;
        uint32_t a0 = __float_as_uint(As[(arow + g)     * lda + ka + t4]);
        uint32_t a1 = __float_as_uint(As[(arow + g + 8) * lda + ka + t4]);
        uint32_t a2 = __float_as_uint(As[(arow + g)     * lda + ka + t4 + 4]);
        uint32_t a3 = __float_as_uint(As[(arow + g + 8) * lda + ka + t4 + 4]);
        const float* bp0 = Bs + (kk + t4)     * LDB + bcol + g;
        const float* bp1 = Bs + (kk + t4 + 4) * LDB + bcol + g;
#pragma unroll
        for (int s = 0; s < 8; s++) {
            mma_tf32(acc[s], a0, a1, a2, a3,
                     __float_as_uint(bp0[s * 8]), __float_as_uint(bp1[s * 8]));
        }
    }
}

extern __shared__ float smem[];

__global__ void __launch_bounds__(THREADS, 1)
grandag_fused_kernel(const float* __restrict__ x,
                     const float* __restrict__ W0,
                     const float* __restrict__ W1,
                     const float* __restrict__ W2,
                     float* __restrict__ out) {
    const int tid  = threadIdx.x;
    const int lane = tid & 31;
    const int warp = tid >> 5;
    const int wm = warp & 3;      // 0..3 (M)
    const int wn = warp >> 2;     // 0..1 (N)
    const int g  = lane >> 2;     // 0..7
    const int t4 = lane & 3;      // 0..3

    const int ntile = blockIdx.x;     // 0..31
    const int d     = blockIdx.y;     // 0..127
    const int n0    = ntile * TN;

    float* xs  = smem + XS_OFF;
    float* h1  = smem + H1_OFF;
    float* bs  = smem + BS_OFF;       // 2 buffers of BS_TILE
    float* w2s = smem + W2_OFF;
    float* outs = smem + OUT_OFF;

    // --- init: w2, outs, masked x tile (tf32-rounded) ---
    if (tid < TN) outs[tid] = 0.0f;
#pragma unroll
    for (int i = tid; i < HID; i += THREADS)
        w2s[i] = W2[(size_t)d * HID + i];

    for (int idx = tid; idx < TN * DNODES; idx += THREADS) {
        int m = idx >> 7;
        int i = idx & 127;
        float v = x[(size_t)(n0 + m) * DNODES + i];
        if (i == d) v = 0.0f;
        xs[m * LDX + i] = to_tf32(v);
    }

    const int arow = wm * 16;
    const int bcol = wn * 64;

    float p0 = 0.0f, p1 = 0.0f;   // fused layer-2 partials (rows arow+g, arow+g+8)
    float4 regs[4];
    float acc[8][4];

    // ================= Layer 0: K=128 (xs) -> h1 =================
    const float* w0base = W0 + (size_t)d * DNODES * HID;
#pragma unroll 1
    for (int nc = 0; nc < 4; nc++) {
#pragma unroll
        for (int s = 0; s < 8; s++)
#pragma unroll
            for (int j = 0; j < 4; j++) acc[s][j] = 0.0f;

        const float* wsrc = w0base + nc * NCHUNK;
        stage_ldg(wsrc, HID, regs, tid);
        __syncthreads();                      // Bs free (covers x/w2/outs init too)
        stage_sts(bs, regs, tid);

        const int T = DNODES / KT;            // 4
#pragma unroll 1
        for (int t = 0; t < T; t++) {
            __syncthreads();
            if (t + 1 < T) stage_ldg(wsrc + (size_t)(t + 1) * KT * HID, HID, regs, tid);
            gemm_tile(xs, LDX, bs + (t & 1) * BS_TILE, acc, t * KT, arow, bcol, g, t4);
            if (t + 1 < T) stage_sts(bs + ((t + 1) & 1) * BS_TILE, regs, tid);
        }

        // epilogue: leaky + tf32 -> h1
        int r0 = arow + g, r1 = r0 + 8;
#pragma unroll
        for (int s = 0; s < 8; s++) {
            int col = nc * NCHUNK + bcol + s * 8 + 2 * t4;
            float2 v0, v1;
            v0.x = to_tf32(leaky(acc[s][0]));
            v0.y = to_tf32(leaky(acc[s][1]));
            v1.x = to_tf32(leaky(acc[s][2]));
            v1.y = to_tf32(leaky(acc[s][3]));
            *reinterpret_cast<float2*>(h1 + r0 * LDH + col) = v0;
            *reinterpret_cast<float2*>(h1 + r1 * LDH + col) = v1;
        }
    }

    // ================= Layer 1: K=512 (h1), fused layer 2 =================
    const float* w1base = W1 + (size_t)d * HID * HID;
#pragma unroll 1
    for (int nc = 0; nc < 4; nc++) {
#pragma unroll
        for (int s = 0; s < 8; s++)
#pragma unroll
            for (int j = 0; j < 4; j++) acc[s][j] = 0.0f;

        const float* wsrc = w1base + nc * NCHUNK;
        stage_ldg(wsrc, HID, regs, tid);
        __syncthreads();                      // Bs free; also h1 complete before first gemm
        stage_sts(bs, regs, tid);

        const int T = HID / KT;               // 16
#pragma unroll 1
        for (int t = 0; t < T; t++) {
            __syncthreads();
            if (t + 1 < T) stage_ldg(wsrc + (size_t)(t + 1) * KT * HID, HID, regs, tid);
            gemm_tile(h1, LDH, bs + (t & 1) * BS_TILE, acc, t * KT, arow, bcol, g, t4);
            if (t + 1 < T) stage_sts(bs + ((t + 1) & 1) * BS_TILE, regs, tid);
        }

        // epilogue: leaky(h2) . W2 accumulated into per-row partials
#pragma unroll
        for (int s = 0; s < 8; s++) {
            int col = nc * NCHUNK + bcol + s * 8 + 2 * t4;
            float w2a = w2s[col], w2b = w2s[col + 1];
            p0 += leaky(acc[s][0]) * w2a + leaky(acc[s][1]) * w2b;
            p1 += leaky(acc[s][2]) * w2a + leaky(acc[s][3]) * w2b;
        }
    }

    // reduce over the 4 lanes of each quad (same row), then across warps via smem
    p0 += __shfl_xor_sync(0xffffffffu, p0, 1);
    p0 += __shfl_xor_sync(0xffffffffu, p0, 2);
    p1 += __shfl_xor_sync(0xffffffffu, p1, 1);
    p1 += __shfl_xor_sync(0xffffffffu, p1, 2);
    if (t4 == 0) {
        atomicAdd(&outs[arow + g],     p0);
        atomicAdd(&outs[arow + g + 8], p1);
    }
    __syncthreads();

    if (tid < TN)
        out[(size_t)(n0 + tid) * DNODES + d] = outs[tid];
}

extern "C" void kernel_launch(void* const* d_in, const int* in_sizes, int n_in,
                              void* d_out, int out_size) {
    (void)in_sizes; (void)n_in; (void)out_size;
    const float* x  = (const float*)d_in[0];
    const float* W0 = (const float*)d_in[1];
    const float* W1 = (const float*)d_in[2];
    const float* W2 = (const float*)d_in[3];
    float* out = (float*)d_out;

    cudaFuncSetAttribute(grandag_fused_kernel,
                         cudaFuncAttributeMaxDynamicSharedMemorySize, SMEM_BYTES);

    dim3 grid(NSAMP / TN, DNODES);   // x fastest -> same-d blocks co-resident (L2 W reuse)
    grandag_fused_kernel<<<grid, THREADS, SMEM_BYTES>>>(x, W0, W1, W2, out);
}